// round 9
// baseline (speedup 1.0000x reference)
#include <cuda_runtime.h>
#include <math.h>
#include <stdint.h>

#define BB 64
#define SS 512
#define FF 128
#define HH 512
#define G4 2048
#define NCTA 128          // persist CTAs
#define NOUT 20           // out-role CTAs
#define NCTAG 32          // CTAs per b-group barrier
#define TPB 512

// Scratch (static device globals — no allocation at kernel_launch time)
__device__ float g_xg[(size_t)SS * BB * G4];    // [S][B][4H] input gates
__device__ float g_hist[(size_t)SS * BB * HH];  // [S][B][H] hidden states
__device__ unsigned g_cnt[4 * SS];              // per-(bgroup,step) counters

// packed dual-fp32 FMA (Blackwell f32x2)
#define FMA2(acc, a, h) asm("fma.rn.f32x2 %0, %1, %2, %0;" : "+l"(acc) : "l"(a), "l"(h))

__device__ __forceinline__ float rsum2(unsigned long long v) {
    float lo, hi;
    asm("mov.b64 {%0,%1}, %2;" : "=f"(lo), "=f"(hi) : "l"(v));
    return lo + hi;
}

#define CP16(dst, src) asm volatile("cp.async.cg.shared.global [%0], [%1], 16;" \
                                    :: "r"(dst), "l"(src))

__global__ void init_kernel() {
    int i = blockIdx.x * blockDim.x + threadIdx.x;
    if (i < 4 * SS) g_cnt[i] = 0;
}

// ---------------------------------------------------------------------------
// x_gates GEMM: g_xg[m][g] = sum_f inputs[b,s,f]*W_ih[g,f] + b_ih[g]+b_hh[g]
// m = s*64+b. M=32768, N=2048, K=128. BM=BN=128, BK=16, 256 thr, 8x8, FMA2.
// ---------------------------------------------------------------------------
__global__ __launch_bounds__(256) void xg_kernel(
    const float* __restrict__ inp, const float* __restrict__ Wih,
    const float* __restrict__ bih, const float* __restrict__ bhh)
{
    __shared__ float As[16][132];
    __shared__ float Bs[16][132];
    const int gBase = blockIdx.x * 128;
    const int mBase = blockIdx.y * 128;
    const int t = threadIdx.x;
    const int tx = t & 15, ty = t >> 4;

    unsigned long long acc[8][4];
    #pragma unroll
    for (int i = 0; i < 8; i++)
        #pragma unroll
        for (int j = 0; j < 4; j++) acc[i][j] = 0ull;

    for (int k0 = 0; k0 < FF; k0 += 16) {
        #pragma unroll
        for (int it = 0; it < 2; it++) {
            int idx = t + (it << 8);
            int row = idx >> 2, c4 = idx & 3;
            int m = mBase + row;
            int b = m & 63, s = m >> 6;
            float4 v = *(const float4*)(inp + ((size_t)b * SS + s) * FF + k0 + (c4 << 2));
            As[c4 * 4 + 0][row] = v.x; As[c4 * 4 + 1][row] = v.y;
            As[c4 * 4 + 2][row] = v.z; As[c4 * 4 + 3][row] = v.w;
        }
        #pragma unroll
        for (int it = 0; it < 2; it++) {
            int idx = t + (it << 8);
            int row = idx >> 2, c4 = idx & 3;
            float4 v = *(const float4*)(Wih + (size_t)(gBase + row) * FF + k0 + (c4 << 2));
            Bs[c4 * 4 + 0][row] = v.x; Bs[c4 * 4 + 1][row] = v.y;
            Bs[c4 * 4 + 2][row] = v.z; Bs[c4 * 4 + 3][row] = v.w;
        }
        __syncthreads();
        #pragma unroll
        for (int kk = 0; kk < 16; kk++) {
            float a[8];
            *(float4*)(a)     = *(const float4*)&As[kk][ty * 8];
            *(float4*)(a + 4) = *(const float4*)&As[kk][ty * 8 + 4];
            ulonglong2 b01 = *(const ulonglong2*)&Bs[kk][tx * 8];
            ulonglong2 b23 = *(const ulonglong2*)&Bs[kk][tx * 8 + 4];
            #pragma unroll
            for (int i = 0; i < 8; i++) {
                unsigned long long a2;
                asm("mov.b64 %0, {%1, %1};" : "=l"(a2) : "f"(a[i]));
                FMA2(acc[i][0], a2, b01.x);
                FMA2(acc[i][1], a2, b01.y);
                FMA2(acc[i][2], a2, b23.x);
                FMA2(acc[i][3], a2, b23.y);
            }
        }
        __syncthreads();
    }

    float bias[8];
    #pragma unroll
    for (int j = 0; j < 8; j++) {
        int g = gBase + tx * 8 + j;
        bias[j] = bih[g] + bhh[g];
    }
    #pragma unroll
    for (int i = 0; i < 8; i++) {
        int m = mBase + ty * 8 + i;
        float f[8];
        #pragma unroll
        for (int jp = 0; jp < 4; jp++)
            asm("mov.b64 {%0,%1}, %2;" : "=f"(f[2*jp]), "=f"(f[2*jp+1]) : "l"(acc[i][jp]));
        float4 o0, o1;
        o0.x = f[0] + bias[0]; o0.y = f[1] + bias[1];
        o0.z = f[2] + bias[2]; o0.w = f[3] + bias[3];
        o1.x = f[4] + bias[4]; o1.y = f[5] + bias[5];
        o1.z = f[6] + bias[6]; o1.w = f[7] + bias[7];
        *(float4*)(g_xg + (size_t)m * G4 + gBase + tx * 8)     = o0;
        *(float4*)(g_xg + (size_t)m * G4 + gBase + tx * 8 + 4) = o1;
    }
}

// ---------------------------------------------------------------------------
// Fused persistent kernel, grid = 148 CTAs:
//   blockIdx.x < 128 : LSTM persist role (32 j-groups x 4 b-groups)
//   blockIdx.x >= 128: out-projection role (consumes per-step counters).
// Persist step pipeline: [h load | compute | red] -> sync ->
//   owners compute gates (warps 0-7) while t==256 polls producers for this
//   step's completion; owners release via bar.sync 9 + red.release; final
//   __syncthreads gates the next step's h load (producers already verified).
// SMEM (floats): ws 32768 | hs 16x516 | xg2 2x1024 | red 256x33
// ---------------------------------------------------------------------------
#define SM_HS   32768
#define SM_XG   41024
#define SM_RED  43072
#define SM_TOT  51520

__global__ __launch_bounds__(TPB, 1) void lstm_persist(
    const float* __restrict__ Whh, const float* __restrict__ Wout,
    const float* __restrict__ bout, float* __restrict__ out)
{
    extern __shared__ float sm[];
    const int t = threadIdx.x;

    if (blockIdx.x >= NCTA) {
        // ------------------- out-projection role -------------------
        float* As = sm;                 // [32][68]
        float* Bs = sm + 32 * 68;       // [32][68]
        const int o = blockIdx.x - NCTA;            // 0..19
        const int tx = t & 31, ty = t >> 5;         // f-pair, m-quad

        for (int tt = o; tt < 2 * SS; tt += NOUT) {
            const int s = tt >> 1;
            const int fBase = (tt & 1) << 6;

            // wait for all 4 b-groups of step s
            if (t < 4) {
                const unsigned* ca = g_cnt + t * SS + s;
                unsigned v;
                do {
                    asm volatile("ld.acquire.gpu.global.u32 %0, [%1];"
                                 : "=r"(v) : "l"(ca) : "memory");
                } while (v < NCTAG);
            }
            __syncthreads();

            float acc[4][2] = {};
            const float* hb = g_hist + ((size_t)s << 15);   // h rows for this s

            for (int k0 = 0; k0 < HH; k0 += 32) {
                {   // 512 threads load 64 rows x 32 k of h (1 float4 each)
                    int row = t >> 3, c4 = t & 7;
                    float4 v = *(const float4*)(hb + ((size_t)row << 9) + k0 + (c4 << 2));
                    As[(c4 * 4 + 0) * 68 + row] = v.x;
                    As[(c4 * 4 + 1) * 68 + row] = v.y;
                    As[(c4 * 4 + 2) * 68 + row] = v.z;
                    As[(c4 * 4 + 3) * 68 + row] = v.w;
                }
                {   // 64 rows x 32 k of W_out
                    int row = t >> 3, c4 = t & 7;
                    float4 v = *(const float4*)(Wout +
                        (size_t)(fBase + row) * HH + k0 + (c4 << 2));
                    Bs[(c4 * 4 + 0) * 68 + row] = v.x;
                    Bs[(c4 * 4 + 1) * 68 + row] = v.y;
                    Bs[(c4 * 4 + 2) * 68 + row] = v.z;
                    Bs[(c4 * 4 + 3) * 68 + row] = v.w;
                }
                __syncthreads();
                #pragma unroll
                for (int kk = 0; kk < 32; kk++) {
                    float a[4], b[2];
                    *(float4*)a = *(const float4*)&As[kk * 68 + ty * 4];
                    b[0] = Bs[kk * 68 + tx * 2];
                    b[1] = Bs[kk * 68 + tx * 2 + 1];
                    #pragma unroll
                    for (int i = 0; i < 4; i++) {
                        acc[i][0] += a[i] * b[0];
                        acc[i][1] += a[i] * b[1];
                    }
                }
                __syncthreads();
            }

            float bias0 = bout[fBase + tx * 2];
            float bias1 = bout[fBase + tx * 2 + 1];
            #pragma unroll
            for (int i = 0; i < 4; i++) {
                int b = ty * 4 + i;           // batch
                float2 ov;
                ov.x = acc[i][0] + bias0;
                ov.y = acc[i][1] + bias1;
                *(float2*)(out + ((size_t)b * SS + s) * FF + fBase + tx * 2) = ov;
            }
        }
        return;
    }

    // ---------------------- LSTM persist role ----------------------
    float* ws  = sm;
    float* hs  = sm + SM_HS;
    float* xg2 = sm + SM_XG;
    float* red = sm + SM_RED;

    const int w = t >> 5, l = t & 31;
    const int jgrp = blockIdx.x >> 2;
    const int bgrp = blockIdx.x & 3;
    const int jg0  = jgrp << 4;
    const int b0   = bgrp << 4;

    const int kq = w >> 1;                     // 0..7
    const int jl = (l & 7) | ((w & 1) << 3);   // 0..15
    const int bq = l >> 3;                     // 0..3
    const int k0 = kq << 6;
    const int k0w = k0 + ((w & 1) << 5);       // this warp's 32-col h slice

    // Load W slice once: ws[row=jl*4+g][k], granule swizzle ^(jl&7)
    for (int i = t; i < 64 * 128; i += TPB) {
        int row = i >> 7, g16 = i & 127;
        int jr = row >> 2, gr = row & 3;
        int pg = g16 ^ (jr & 7);
        *(float4*)&ws[(row << 9) + (pg << 2)] =
            *(const float4*)&Whh[((size_t)(gr * HH + jg0 + jr) << 9) + (g16 << 2)];
    }

    // Prefetch xg(0) and xg(1) (warps 0-7), separate commit groups
    if (t < 256) {
        int bi = t >> 4, cc = t & 15;
        int g = cc >> 2, j4 = cc & 3;
        {
            const float* src = g_xg + (size_t)(b0 + bi) * G4 + g * HH + jg0 + (j4 << 2);
            uint32_t d = (uint32_t)__cvta_generic_to_shared(
                &xg2[((g << 4) + bi) * 16 + (j4 << 2)]);
            CP16(d, src);
            asm volatile("cp.async.commit_group;");
        }
        {
            const float* src = g_xg + (size_t)(BB + b0 + bi) * G4 + g * HH + jg0 + (j4 << 2);
            uint32_t d = (uint32_t)__cvta_generic_to_shared(
                &xg2[1024 + ((g << 4) + bi) * 16 + (j4 << 2)]);
            CP16(d, src);
            asm volatile("cp.async.commit_group;");
        }
    }
    __syncthreads();

    const float* wq0 = ws + ((jl * 4 + 0) << 9);
    const float* wq1 = ws + ((jl * 4 + 1) << 9);
    const float* wq2 = ws + ((jl * 4 + 2) << 9);
    const float* wq3 = ws + ((jl * 4 + 3) << 9);
    const int xr = (jl & 7) << 2;

    float c = 0.f;

    for (int s = 0; s < SS; s++) {
        if (s > 0) {
            // producers for step s-1 were verified by t==256's poll last
            // iteration; the trailing __syncthreads makes that visible here.

            // per-warp h slice: 16 batches x 32 k-cols
            {
                const float* hp = g_hist + ((size_t)(s - 1) << 15);
                #pragma unroll
                for (int it = 0; it < 4; it++) {
                    int idx = (it << 5) + l;
                    int r = idx >> 3, c4 = idx & 7;
                    int col = k0w + (c4 << 2);
                    uint32_t d = (uint32_t)__cvta_generic_to_shared(&hs[r * 516 + col]);
                    CP16(d, hp + (((size_t)(b0 + r)) << 9) + col);
                }
                asm volatile("cp.async.commit_group;");
                asm volatile("cp.async.wait_group 0;");
                asm volatile("bar.sync %0, 64;" :: "r"(kq + 1));
            }

            // Prefetch xg(s+1) during compute (warps 0-7 only)
            if (t < 256 && s + 1 < SS) {
                int bi = t >> 4, cc = t & 15;
                int g = cc >> 2, j4 = cc & 3;
                const float* src = g_xg +
                    (size_t)((s + 1) * BB + b0 + bi) * G4 + g * HH + jg0 + (j4 << 2);
                uint32_t d = (uint32_t)__cvta_generic_to_shared(
                    &xg2[(((s + 1) & 1) << 10) + ((g << 4) + bi) * 16 + (j4 << 2)]);
                CP16(d, src);
                asm volatile("cp.async.commit_group;");
            }

            unsigned long long A0[4], A1[4], A2[4], A3[4];
            #pragma unroll
            for (int i = 0; i < 4; i++) { A0[i] = 0; A1[i] = 0; A2[i] = 0; A3[i] = 0; }

            #pragma unroll 4
            for (int k = k0; k < k0 + 64; k += 4) {
                int kx = k ^ xr;
                ulonglong2 w0 = *(const ulonglong2*)(wq0 + kx);
                ulonglong2 w1 = *(const ulonglong2*)(wq1 + kx);
                ulonglong2 w2 = *(const ulonglong2*)(wq2 + kx);
                ulonglong2 w3 = *(const ulonglong2*)(wq3 + kx);
                #pragma unroll
                for (int i = 0; i < 4; i++) {
                    ulonglong2 hv = *(const ulonglong2*)(hs + (i * 4 + bq) * 516 + k);
                    FMA2(A0[i], w0.x, hv.x); FMA2(A0[i], w0.y, hv.y);
                    FMA2(A1[i], w1.x, hv.x); FMA2(A1[i], w1.y, hv.y);
                    FMA2(A2[i], w2.x, hv.x); FMA2(A2[i], w2.y, hv.y);
                    FMA2(A3[i], w3.x, hv.x); FMA2(A3[i], w3.y, hv.y);
                }
            }
            // partials: red[(b*16+j)*33 + kq*4+g]
            const int rr = kq << 2;
            #pragma unroll
            for (int i = 0; i < 4; i++) {
                int base = ((i * 4 + bq) * 16 + jl) * 33 + rr;
                red[base + 0] = rsum2(A0[i]);
                red[base + 1] = rsum2(A1[i]);
                red[base + 2] = rsum2(A2[i]);
                red[base + 3] = rsum2(A3[i]);
            }
        } else {
            // xg(0) must be resident (xg(1) may still be in flight)
            if (t < 256) asm volatile("cp.async.wait_group 1;");
        }
        __syncthreads();   // red ready; hs reads complete

        if (t < 256) {
            // ---------------- owner phase (warps 0-7) ----------------
            const int jo = t & 15, bo = t >> 4;
            const float* xb = xg2 + ((s & 1) << 10);
            float a0 = xb[       (bo << 4) + jo];
            float a1 = xb[256 +  (bo << 4) + jo];
            float a2 = xb[512 +  (bo << 4) + jo];
            float a3 = xb[768 +  (bo << 4) + jo];
            if (s > 0) {
                const float* rp = red + ((bo << 4) + jo) * 33;
                #pragma unroll
                for (int q = 0; q < 8; q++) {
                    a0 += rp[q * 4 + 0];
                    a1 += rp[q * 4 + 1];
                    a2 += rp[q * 4 + 2];
                    a3 += rp[q * 4 + 3];
                }
            }
            float ig = 1.f / (1.f + __expf(-a0));
            float fg = 1.f / (1.f + __expf(-a1));
            float gg = 2.f / (1.f + __expf(-2.f * a2)) - 1.f;
            float og = 1.f / (1.f + __expf(-a3));
            c = fg * c + ig * gg;
            float th = 2.f / (1.f + __expf(-2.f * c)) - 1.f;
            g_hist[((size_t)(s * BB + b0 + bo) << 9) + jg0 + jo] = og * th;

            // owners-only barrier, then release this step's counter
            asm volatile("bar.sync 9, 256;");
            if (t == 0)
                asm volatile("red.release.gpu.global.add.u32 [%0], %1;"
                             :: "l"(g_cnt + bgrp * SS + s), "r"(1u) : "memory");
        } else if (t == 256) {
            // ------------- overlapped producer poll (warp 8) -------------
            // Wait for all 32 CTAs of this b-group to finish step s, while
            // owners of this CTA are still computing.  Our own release comes
            // via bar9 (warps 0-7) and does not involve this thread.
            const unsigned* ca = g_cnt + bgrp * SS + s;
            unsigned v;
            do {
                asm volatile("ld.acquire.gpu.global.u32 %0, [%1];"
                             : "=r"(v) : "l"(ca) : "memory");
            } while (v < NCTAG);
        }
        __syncthreads();   // owners released + producers verified -> next step
    }
}

extern "C" void kernel_launch(void* const* d_in, const int* in_sizes, int n_in,
                              void* d_out, int out_size)
{
    const float* inp  = (const float*)d_in[0];
    const float* Wih  = (const float*)d_in[1];
    const float* Whh  = (const float*)d_in[2];
    const float* bih  = (const float*)d_in[3];
    const float* bhh  = (const float*)d_in[4];
    const float* Wout = (const float*)d_in[5];
    const float* bout = (const float*)d_in[6];
    float* out = (float*)d_out;

    const int smem_bytes = SM_TOT * 4;  // 206,080 B
    cudaFuncSetAttribute(lstm_persist,
                         cudaFuncAttributeMaxDynamicSharedMemorySize, smem_bytes);

    init_kernel<<<8, 256>>>();
    xg_kernel<<<dim3(G4 / 128, (SS * BB) / 128), 256>>>(inp, Wih, bih, bhh);
    lstm_persist<<<NCTA + NOUT, TPB, smem_bytes>>>(Whh, Wout, bout, out);
}

// round 10
// speedup vs baseline: 1.6034x; 1.6034x over previous
#include <cuda_runtime.h>
#include <math.h>
#include <stdint.h>

#define BB 64
#define SS 512
#define FF 128
#define HH 512
#define G4 2048
#define NCTA 128          // persist CTAs
#define NOUT 20           // out-role CTAs
#define NCTAG 32          // CTAs per b-group barrier
#define TPB 512

// Scratch (static device globals — no allocation at kernel_launch time)
__device__ float g_xg[(size_t)SS * BB * G4];    // [S][B][4H] input gates
__device__ float g_hist[(size_t)SS * BB * HH];  // [S][B][H] hidden states fp32
__device__ unsigned g_htf[2 * BB * HH];         // h in tf32 bits, double buffer
__device__ unsigned g_cnt[4 * SS];              // per-(bgroup,step) counters

// packed dual-fp32 FMA (Blackwell f32x2)
#define FMA2(acc, a, h) asm("fma.rn.f32x2 %0, %1, %2, %0;" : "+l"(acc) : "l"(a), "l"(h))

#define CP16(dst, src) asm volatile("cp.async.cg.shared.global [%0], [%1], 16;" \
                                    :: "r"(dst), "l"(src))

#define MMA_TF32(C, A, b0r, b1r) \
    asm volatile("mma.sync.aligned.m16n8k8.row.col.f32.tf32.tf32.f32 " \
        "{%0,%1,%2,%3}, {%4,%5,%6,%7}, {%8,%9}, {%0,%1,%2,%3};" \
        : "+f"(C[0]), "+f"(C[1]), "+f"(C[2]), "+f"(C[3]) \
        : "r"(A[0]), "r"(A[1]), "r"(A[2]), "r"(A[3]), "r"(b0r), "r"(b1r))

__device__ __forceinline__ unsigned f2tf32(float f) {
    unsigned u;
    asm("cvt.rna.tf32.f32 %0, %1;" : "=r"(u) : "f"(f));
    return u;
}

__global__ void init_kernel() {
    int i = blockIdx.x * blockDim.x + threadIdx.x;
    if (i < 4 * SS) g_cnt[i] = 0;
}

// ---------------------------------------------------------------------------
// x_gates GEMM: g_xg[m][g] = sum_f inputs[b,s,f]*W_ih[g,f] + b_ih[g]+b_hh[g]
// m = s*64+b. M=32768, N=2048, K=128. BM=BN=128, BK=16, 256 thr, 8x8, FMA2.
// ---------------------------------------------------------------------------
__global__ __launch_bounds__(256) void xg_kernel(
    const float* __restrict__ inp, const float* __restrict__ Wih,
    const float* __restrict__ bih, const float* __restrict__ bhh)
{
    __shared__ float As[16][132];
    __shared__ float Bs[16][132];
    const int gBase = blockIdx.x * 128;
    const int mBase = blockIdx.y * 128;
    const int t = threadIdx.x;
    const int tx = t & 15, ty = t >> 4;

    unsigned long long acc[8][4];
    #pragma unroll
    for (int i = 0; i < 8; i++)
        #pragma unroll
        for (int j = 0; j < 4; j++) acc[i][j] = 0ull;

    for (int k0 = 0; k0 < FF; k0 += 16) {
        #pragma unroll
        for (int it = 0; it < 2; it++) {
            int idx = t + (it << 8);
            int row = idx >> 2, c4 = idx & 3;
            int m = mBase + row;
            int b = m & 63, s = m >> 6;
            float4 v = *(const float4*)(inp + ((size_t)b * SS + s) * FF + k0 + (c4 << 2));
            As[c4 * 4 + 0][row] = v.x; As[c4 * 4 + 1][row] = v.y;
            As[c4 * 4 + 2][row] = v.z; As[c4 * 4 + 3][row] = v.w;
        }
        #pragma unroll
        for (int it = 0; it < 2; it++) {
            int idx = t + (it << 8);
            int row = idx >> 2, c4 = idx & 3;
            float4 v = *(const float4*)(Wih + (size_t)(gBase + row) * FF + k0 + (c4 << 2));
            Bs[c4 * 4 + 0][row] = v.x; Bs[c4 * 4 + 1][row] = v.y;
            Bs[c4 * 4 + 2][row] = v.z; Bs[c4 * 4 + 3][row] = v.w;
        }
        __syncthreads();
        #pragma unroll
        for (int kk = 0; kk < 16; kk++) {
            float a[8];
            *(float4*)(a)     = *(const float4*)&As[kk][ty * 8];
            *(float4*)(a + 4) = *(const float4*)&As[kk][ty * 8 + 4];
            ulonglong2 b01 = *(const ulonglong2*)&Bs[kk][tx * 8];
            ulonglong2 b23 = *(const ulonglong2*)&Bs[kk][tx * 8 + 4];
            #pragma unroll
            for (int i = 0; i < 8; i++) {
                unsigned long long a2;
                asm("mov.b64 %0, {%1, %1};" : "=l"(a2) : "f"(a[i]));
                FMA2(acc[i][0], a2, b01.x);
                FMA2(acc[i][1], a2, b01.y);
                FMA2(acc[i][2], a2, b23.x);
                FMA2(acc[i][3], a2, b23.y);
            }
        }
        __syncthreads();
    }

    float bias[8];
    #pragma unroll
    for (int j = 0; j < 8; j++) {
        int g = gBase + tx * 8 + j;
        bias[j] = bih[g] + bhh[g];
    }
    #pragma unroll
    for (int i = 0; i < 8; i++) {
        int m = mBase + ty * 8 + i;
        float f[8];
        #pragma unroll
        for (int jp = 0; jp < 4; jp++)
            asm("mov.b64 {%0,%1}, %2;" : "=f"(f[2*jp]), "=f"(f[2*jp+1]) : "l"(acc[i][jp]));
        float4 o0, o1;
        o0.x = f[0] + bias[0]; o0.y = f[1] + bias[1];
        o0.z = f[2] + bias[2]; o0.w = f[3] + bias[3];
        o1.x = f[4] + bias[4]; o1.y = f[5] + bias[5];
        o1.z = f[6] + bias[6]; o1.w = f[7] + bias[7];
        *(float4*)(g_xg + (size_t)m * G4 + gBase + tx * 8)     = o0;
        *(float4*)(g_xg + (size_t)m * G4 + gBase + tx * 8 + 4) = o1;
    }
}

// ---------------------------------------------------------------------------
// Fused persistent kernel, grid = 148 CTAs:
//   blockIdx.x < 128 : LSTM persist (32 j-groups x 4 b-groups), tf32 mma.
//     16 warps = kw (k-split, 0..3) x mw (m-split, 0..3).  Warp (kw,mw) owns
//     A rows [mw*16,mw*16+16) x k [kw*128,kw*128+128), fragments RESIDENT in
//     registers for all 512 steps (W_hh never reloaded).  Per step: h slice
//     (tf32, from g_htf double buffer) via cp.async, 32 mma per warp,
//     partials to red SMEM, owner warps finish gates.
//   blockIdx.x >= 128: out-projection role (consumes per-step counters).
// SMEM (floats): hs 16x516 (tf32 bits) | xg2 2x1024 | red 256x20
// ---------------------------------------------------------------------------
#define SM_HS   0
#define SM_XG   8256
#define SM_RED  10304
#define SM_TOT  15424

__global__ __launch_bounds__(TPB, 1) void lstm_persist(
    const float* __restrict__ Whh, const float* __restrict__ Wout,
    const float* __restrict__ bout, float* __restrict__ out)
{
    extern __shared__ float sm[];
    const int t = threadIdx.x;

    if (blockIdx.x >= NCTA) {
        // ------------------- out-projection role -------------------
        float* As = sm;                 // [32][68]
        float* Bs = sm + 32 * 68;       // [32][68]
        const int o = blockIdx.x - NCTA;            // 0..19
        const int tx = t & 31, ty = t >> 5;         // f-pair, m-quad

        for (int tt = o; tt < 2 * SS; tt += NOUT) {
            const int s = tt >> 1;
            const int fBase = (tt & 1) << 6;

            if (t < 4) {
                const unsigned* ca = g_cnt + t * SS + s;
                unsigned v;
                do {
                    asm volatile("ld.acquire.gpu.global.u32 %0, [%1];"
                                 : "=r"(v) : "l"(ca) : "memory");
                } while (v < NCTAG);
            }
            __syncthreads();

            float acc[4][2] = {};
            const float* hb = g_hist + ((size_t)s << 15);

            for (int k0 = 0; k0 < HH; k0 += 32) {
                {
                    int row = t >> 3, c4 = t & 7;
                    float4 v = *(const float4*)(hb + ((size_t)row << 9) + k0 + (c4 << 2));
                    As[(c4 * 4 + 0) * 68 + row] = v.x;
                    As[(c4 * 4 + 1) * 68 + row] = v.y;
                    As[(c4 * 4 + 2) * 68 + row] = v.z;
                    As[(c4 * 4 + 3) * 68 + row] = v.w;
                }
                {
                    int row = t >> 3, c4 = t & 7;
                    float4 v = *(const float4*)(Wout +
                        (size_t)(fBase + row) * HH + k0 + (c4 << 2));
                    Bs[(c4 * 4 + 0) * 68 + row] = v.x;
                    Bs[(c4 * 4 + 1) * 68 + row] = v.y;
                    Bs[(c4 * 4 + 2) * 68 + row] = v.z;
                    Bs[(c4 * 4 + 3) * 68 + row] = v.w;
                }
                __syncthreads();
                #pragma unroll
                for (int kk = 0; kk < 32; kk++) {
                    float a[4], b[2];
                    *(float4*)a = *(const float4*)&As[kk * 68 + ty * 4];
                    b[0] = Bs[kk * 68 + tx * 2];
                    b[1] = Bs[kk * 68 + tx * 2 + 1];
                    #pragma unroll
                    for (int i = 0; i < 4; i++) {
                        acc[i][0] += a[i] * b[0];
                        acc[i][1] += a[i] * b[1];
                    }
                }
                __syncthreads();
            }

            float bias0 = bout[fBase + tx * 2];
            float bias1 = bout[fBase + tx * 2 + 1];
            #pragma unroll
            for (int i = 0; i < 4; i++) {
                int b = ty * 4 + i;
                float2 ov;
                ov.x = acc[i][0] + bias0;
                ov.y = acc[i][1] + bias1;
                *(float2*)(out + ((size_t)b * SS + s) * FF + fBase + tx * 2) = ov;
            }
        }
        return;
    }

    // ---------------------- LSTM persist role ----------------------
    unsigned* hsu = (unsigned*)(sm + SM_HS);   // h tile, tf32 bits, pitch 516
    float* xg2 = sm + SM_XG;
    float* red = sm + SM_RED;                  // [b*16+j][20]: kw*4+g

    const int w = t >> 5, l = t & 31;
    const int kw = w >> 2, mw = w & 3;         // k-split, m-split
    const int gid = l >> 2, tig = l & 3;       // mma lane decode
    const int jgrp = blockIdx.x >> 2;
    const int bgrp = blockIdx.x & 3;
    const int jg0  = jgrp << 4;
    const int b0   = bgrp << 4;

    // Resident A fragments: W rows m = jl*4+g (jl = m>>2, g = m&3),
    // Whh row = g*HH + jg0 + jl.  m16n8k8 tf32 layout.
    unsigned Af[16][4];
    {
        int m0 = (mw << 4) + gid;
        int m1 = m0 + 8;
        const float* r0 = Whh + (size_t)((m0 & 3) * HH + jg0 + (m0 >> 2)) * HH;
        const float* r1 = Whh + (size_t)((m1 & 3) * HH + jg0 + (m1 >> 2)) * HH;
        #pragma unroll
        for (int kt = 0; kt < 16; kt++) {
            int kc = (kw << 7) + (kt << 3) + tig;
            Af[kt][0] = f2tf32(__ldg(r0 + kc));
            Af[kt][1] = f2tf32(__ldg(r1 + kc));
            Af[kt][2] = f2tf32(__ldg(r0 + kc + 4));
            Af[kt][3] = f2tf32(__ldg(r1 + kc + 4));
        }
    }

    // Prefetch xg(0) and xg(1) (warps 0-7), separate commit groups
    if (t < 256) {
        int bi = t >> 4, cc = t & 15;
        int g = cc >> 2, j4 = cc & 3;
        {
            const float* src = g_xg + (size_t)(b0 + bi) * G4 + g * HH + jg0 + (j4 << 2);
            uint32_t d = (uint32_t)__cvta_generic_to_shared(
                &xg2[((g << 4) + bi) * 16 + (j4 << 2)]);
            CP16(d, src);
            asm volatile("cp.async.commit_group;");
        }
        {
            const float* src = g_xg + (size_t)(BB + b0 + bi) * G4 + g * HH + jg0 + (j4 << 2);
            uint32_t d = (uint32_t)__cvta_generic_to_shared(
                &xg2[1024 + ((g << 4) + bi) * 16 + (j4 << 2)]);
            CP16(d, src);
            asm volatile("cp.async.commit_group;");
        }
    }
    __syncthreads();

    float c = 0.f;

    for (int s = 0; s < SS; s++) {
        if (s > 0) {
            // h slice (tf32): warp (kw,mw) loads 16 rows x 32 cols
            {
                const unsigned* hp = g_htf + (((s - 1) & 1) << 15);
                #pragma unroll
                for (int it = 0; it < 4; it++) {
                    int idx = (it << 5) + l;
                    int r = idx >> 3, c8 = idx & 7;
                    int col = (kw << 7) + (mw << 5) + (c8 << 2);
                    uint32_t d = (uint32_t)__cvta_generic_to_shared(
                        &hsu[r * 516 + col]);
                    CP16(d, hp + (((b0 + r)) << 9) + col);
                }
                asm volatile("cp.async.commit_group;");
                asm volatile("cp.async.wait_group 0;");
                asm volatile("bar.sync %0, 128;" :: "r"(kw + 1));
            }

            // Prefetch xg(s+1) during compute (warps 0-7 only)
            if (t < 256 && s + 1 < SS) {
                int bi = t >> 4, cc = t & 15;
                int g = cc >> 2, j4 = cc & 3;
                const float* src = g_xg +
                    (size_t)((s + 1) * BB + b0 + bi) * G4 + g * HH + jg0 + (j4 << 2);
                uint32_t d = (uint32_t)__cvta_generic_to_shared(
                    &xg2[(((s + 1) & 1) << 10) + ((g << 4) + bi) * 16 + (j4 << 2)]);
                CP16(d, src);
                asm volatile("cp.async.commit_group;");
            }

            // 32 mma: ntile0 = batches gid row-block, ntile1 = +8
            float C0[4] = {0.f, 0.f, 0.f, 0.f};
            float C1[4] = {0.f, 0.f, 0.f, 0.f};
            const unsigned* hb0 = hsu + gid * 516 + (kw << 7) + tig;
            const unsigned* hb1 = hsu + (gid + 8) * 516 + (kw << 7) + tig;
            #pragma unroll
            for (int kt = 0; kt < 16; kt++) {
                unsigned b0r = hb0[kt << 3];
                unsigned b1r = hb0[(kt << 3) + 4];
                MMA_TF32(C0, Af[kt], b0r, b1r);
                unsigned b2r = hb1[kt << 3];
                unsigned b3r = hb1[(kt << 3) + 4];
                MMA_TF32(C1, Af[kt], b2r, b3r);
            }

            // partials: red[(b*16+jl)*20 + kw*4+g]
            {
                const int jlA = (mw << 2) + (gid >> 2);
                const int gA  = gid & 3;
                const int bA  = tig << 1;
                const int cA  = (kw << 2) + gA;
                red[((bA)     * 16 + jlA)     * 20 + cA] = C0[0];
                red[((bA + 1) * 16 + jlA)     * 20 + cA] = C0[1];
                red[((bA)     * 16 + jlA + 2) * 20 + cA] = C0[2];
                red[((bA + 1) * 16 + jlA + 2) * 20 + cA] = C0[3];
                red[((bA + 8) * 16 + jlA)     * 20 + cA] = C1[0];
                red[((bA + 9) * 16 + jlA)     * 20 + cA] = C1[1];
                red[((bA + 8) * 16 + jlA + 2) * 20 + cA] = C1[2];
                red[((bA + 9) * 16 + jlA + 2) * 20 + cA] = C1[3];
            }
        } else {
            // xg(0) must be resident (xg(1) may still be in flight)
            if (t < 256) asm volatile("cp.async.wait_group 1;");
        }
        __syncthreads();   // red ready; hs reads complete

        if (t < 256) {
            // ---------------- owner phase (warps 0-7) ----------------
            const int jo = t & 15, bo = t >> 4;
            const float* xb = xg2 + ((s & 1) << 10);
            float a0 = xb[       (bo << 4) + jo];
            float a1 = xb[256 +  (bo << 4) + jo];
            float a2 = xb[512 +  (bo << 4) + jo];
            float a3 = xb[768 +  (bo << 4) + jo];
            if (s > 0) {
                const float4* rp = (const float4*)(red + t * 20);
                float4 q0 = rp[0], q1 = rp[1], q2 = rp[2], q3 = rp[3];
                a0 += q0.x + q1.x + q2.x + q3.x;
                a1 += q0.y + q1.y + q2.y + q3.y;
                a2 += q0.z + q1.z + q2.z + q3.z;
                a3 += q0.w + q1.w + q2.w + q3.w;
            }
            float ig = 1.f / (1.f + __expf(-a0));
            float fg = 1.f / (1.f + __expf(-a1));
            float gg = 2.f / (1.f + __expf(-2.f * a2)) - 1.f;
            float og = 1.f / (1.f + __expf(-a3));
            c = fg * c + ig * gg;
            float th = 2.f / (1.f + __expf(-2.f * c)) - 1.f;
            float h = og * th;
            g_hist[((size_t)(s * BB + b0 + bo) << 9) + jg0 + jo] = h;
            g_htf[((s & 1) << 15) + ((b0 + bo) << 9) + jg0 + jo] = f2tf32(h);

            // owners-only barrier, then release this step's counter
            asm volatile("bar.sync 9, 256;");
            if (t == 0)
                asm volatile("red.release.gpu.global.add.u32 [%0], %1;"
                             :: "l"(g_cnt + bgrp * SS + s), "r"(1u) : "memory");
        } else if (t == 256) {
            // overlapped producer poll (lane 0 of warp 8)
            const unsigned* ca = g_cnt + bgrp * SS + s;
            unsigned v;
            do {
                asm volatile("ld.acquire.gpu.global.u32 %0, [%1];"
                             : "=r"(v) : "l"(ca) : "memory");
            } while (v < NCTAG);
        }
        __syncthreads();   // owners released + producers verified -> next step
    }
}

extern "C" void kernel_launch(void* const* d_in, const int* in_sizes, int n_in,
                              void* d_out, int out_size)
{
    const float* inp  = (const float*)d_in[0];
    const float* Wih  = (const float*)d_in[1];
    const float* Whh  = (const float*)d_in[2];
    const float* bih  = (const float*)d_in[3];
    const float* bhh  = (const float*)d_in[4];
    const float* Wout = (const float*)d_in[5];
    const float* bout = (const float*)d_in[6];
    float* out = (float*)d_out;

    const int smem_bytes = SM_TOT * 4;  // 61,696 B
    cudaFuncSetAttribute(lstm_persist,
                         cudaFuncAttributeMaxDynamicSharedMemorySize, smem_bytes);

    init_kernel<<<8, 256>>>();
    xg_kernel<<<dim3(G4 / 128, (SS * BB) / 128), 256>>>(inp, Wih, bih, bhh);
    lstm_persist<<<NCTA + NOUT, TPB, smem_bytes>>>(Whh, Wout, bout, out);
}

// round 11
// speedup vs baseline: 1.7747x; 1.1069x over previous
#include <cuda_runtime.h>
#include <math.h>
#include <stdint.h>

#define BB 64
#define SS 512
#define FF 128
#define HH 512
#define G4 2048
#define NCTA 128          // persist CTAs
#define NOUT 20           // out-role CTAs
#define NCTAG 32          // CTAs per b-group barrier
#define TPB 512

// Scratch (static device globals — no allocation at kernel_launch time)
__device__ float g_xg[(size_t)SS * BB * G4];    // [S][B][4H] input gates
__device__ float g_hist[(size_t)SS * BB * HH];  // [S][B][H] h (tf32-rounded fp32)
__device__ unsigned g_cnt[4 * SS];              // per-(bgroup,step) counters

#define CP16(dst, src) asm volatile("cp.async.cg.shared.global [%0], [%1], 16;" \
                                    :: "r"(dst), "l"(src))

#define MMA_TF32(C, A, b0r, b1r) \
    asm volatile("mma.sync.aligned.m16n8k8.row.col.f32.tf32.tf32.f32 " \
        "{%0,%1,%2,%3}, {%4,%5,%6,%7}, {%8,%9}, {%0,%1,%2,%3};" \
        : "+f"(C[0]), "+f"(C[1]), "+f"(C[2]), "+f"(C[3]) \
        : "r"(A[0]), "r"(A[1]), "r"(A[2]), "r"(A[3]), "r"(b0r), "r"(b1r))

__device__ __forceinline__ unsigned f2tf32(float f) {
    unsigned u;
    asm("cvt.rna.tf32.f32 %0, %1;" : "=r"(u) : "f"(f));
    return u;
}

__global__ void init_kernel() {
    int i = blockIdx.x * blockDim.x + threadIdx.x;
    if (i < 4 * SS) g_cnt[i] = 0;
}

// ---------------------------------------------------------------------------
// x_gates GEMM on tensor cores (tf32), mirroring the persist mma mapping.
// C[g][m] = sum_f Wih[g,f]*inp[m,f];  g_xg[m][g] = C + bias.
// Grid (32 g-groups, 64 m-chunks).  CTA: 64 g x 512 m, 8 subtiles of 64 m.
// 8 warps = aw(4 g-tiles of 16) x nh(2 n-halves of 32).  A frags resident.
// SMEM floats: hsx 64x132 | cs 64x68 | bs 64
// ---------------------------------------------------------------------------
#define XG_HS  0
#define XG_CS  8448
#define XG_BS  12800
#define XG_TOT 12864

__global__ __launch_bounds__(256) void xg_tc(
    const float* __restrict__ inp, const float* __restrict__ Wih,
    const float* __restrict__ bih, const float* __restrict__ bhh)
{
    extern __shared__ float sx[];
    float* hsx = sx + XG_HS;
    float* cs  = sx + XG_CS;
    float* bs  = sx + XG_BS;

    const int t = threadIdx.x;
    const int w = t >> 5, l = t & 31;
    const int gid = l >> 2, tig = l & 3;
    const int aw = w >> 1, nh = w & 1;
    const int gBase = blockIdx.x << 6;

    if (t < 64) bs[t] = bih[gBase + t] + bhh[gBase + t];

    // Resident A fragments: W rows m0,m1 of this warp's g-tile
    unsigned Af[16][4];
    {
        const int m0 = (aw << 4) + gid;
        const float* r0 = Wih + (size_t)(gBase + m0) * FF;
        const float* r1 = Wih + (size_t)(gBase + m0 + 8) * FF;
        #pragma unroll
        for (int kt = 0; kt < 16; kt++) {
            int kc = (kt << 3) + tig;
            Af[kt][0] = f2tf32(__ldg(r0 + kc));
            Af[kt][1] = f2tf32(__ldg(r1 + kc));
            Af[kt][2] = f2tf32(__ldg(r0 + kc + 4));
            Af[kt][3] = f2tf32(__ldg(r1 + kc + 4));
        }
    }

    for (int sub = 0; sub < 8; sub++) {
        const int sfix = (blockIdx.y << 3) + sub;

        // load inp subtile: 64 batches x 128 k (rows = batches at fixed s)
        #pragma unroll
        for (int it = 0; it < 8; it++) {
            int idx = t + (it << 8);
            int r = idx >> 5, c4 = idx & 31;
            uint32_t d = (uint32_t)__cvta_generic_to_shared(&hsx[r * 132 + (c4 << 2)]);
            CP16(d, inp + ((size_t)r * SS + sfix) * FF + (c4 << 2));
        }
        asm volatile("cp.async.commit_group;");
        asm volatile("cp.async.wait_group 0;");
        __syncthreads();

        float C[4][4] = {};
        #pragma unroll
        for (int nt = 0; nt < 4; nt++) {
            const unsigned* hb = (const unsigned*)hsx +
                (((nh << 5) + (nt << 3) + gid) * 132 + tig);
            #pragma unroll
            for (int kt = 0; kt < 16; kt++) {
                unsigned b0r = hb[kt << 3];
                unsigned b1r = hb[(kt << 3) + 4];
                MMA_TF32(C[nt], Af[kt], b0r, b1r);
            }
        }

        // stage C -> cs[mrow][g]
        const int grow = (aw << 4) + gid;
        #pragma unroll
        for (int nt = 0; nt < 4; nt++) {
            int base = (nh << 5) + (nt << 3) + (tig << 1);
            cs[ base      * 68 + grow    ] = C[nt][0];
            cs[(base + 1) * 68 + grow    ] = C[nt][1];
            cs[ base      * 68 + grow + 8] = C[nt][2];
            cs[(base + 1) * 68 + grow + 8] = C[nt][3];
        }
        __syncthreads();

        // coalesced store with bias: 64 rows x 64 g
        #pragma unroll
        for (int it = 0; it < 4; it++) {
            int idx = t + (it << 8);
            int row = idx >> 4, c4 = idx & 15;
            float4 v = *(const float4*)&cs[row * 68 + (c4 << 2)];
            float4 bb = *(const float4*)&bs[c4 << 2];
            v.x += bb.x; v.y += bb.y; v.z += bb.z; v.w += bb.w;
            *(float4*)(g_xg + (size_t)((sfix << 6) + row) * G4 + gBase + (c4 << 2)) = v;
        }
        __syncthreads();
    }
}

// ---------------------------------------------------------------------------
// Fused persistent kernel, grid = 148 CTAs (see R10).  h stored tf32-rounded
// in g_hist; consumers feed those bits directly to mma.
// SMEM (floats): hs 16x516 | xg2 2x1024 | red 256x20
// ---------------------------------------------------------------------------
#define SM_HS   0
#define SM_XG   8256
#define SM_RED  10304
#define SM_TOT  15424

__global__ __launch_bounds__(TPB, 1) void lstm_persist(
    const float* __restrict__ Whh, const float* __restrict__ Wout,
    const float* __restrict__ bout, float* __restrict__ out)
{
    extern __shared__ float sm[];
    const int t = threadIdx.x;

    if (blockIdx.x >= NCTA) {
        // ------------------- out-projection role -------------------
        float* As = sm;                 // [32][68]
        float* Bs = sm + 32 * 68;       // [32][68]
        const int o = blockIdx.x - NCTA;            // 0..19
        const int tx = t & 31, ty = t >> 5;         // f-pair, m-quad

        for (int tt = o; tt < 2 * SS; tt += NOUT) {
            const int s = tt >> 1;
            const int fBase = (tt & 1) << 6;

            if (t < 4) {
                const unsigned* ca = g_cnt + t * SS + s;
                unsigned v;
                do {
                    asm volatile("ld.acquire.gpu.global.u32 %0, [%1];"
                                 : "=r"(v) : "l"(ca) : "memory");
                } while (v < NCTAG);
            }
            __syncthreads();

            float acc[4][2] = {};
            const float* hb = g_hist + ((size_t)s << 15);

            for (int k0 = 0; k0 < HH; k0 += 32) {
                {
                    int row = t >> 3, c4 = t & 7;
                    float4 v = *(const float4*)(hb + ((size_t)row << 9) + k0 + (c4 << 2));
                    As[(c4 * 4 + 0) * 68 + row] = v.x;
                    As[(c4 * 4 + 1) * 68 + row] = v.y;
                    As[(c4 * 4 + 2) * 68 + row] = v.z;
                    As[(c4 * 4 + 3) * 68 + row] = v.w;
                }
                {
                    int row = t >> 3, c4 = t & 7;
                    float4 v = *(const float4*)(Wout +
                        (size_t)(fBase + row) * HH + k0 + (c4 << 2));
                    Bs[(c4 * 4 + 0) * 68 + row] = v.x;
                    Bs[(c4 * 4 + 1) * 68 + row] = v.y;
                    Bs[(c4 * 4 + 2) * 68 + row] = v.z;
                    Bs[(c4 * 4 + 3) * 68 + row] = v.w;
                }
                __syncthreads();
                #pragma unroll
                for (int kk = 0; kk < 32; kk++) {
                    float a[4], b[2];
                    *(float4*)a = *(const float4*)&As[kk * 68 + ty * 4];
                    b[0] = Bs[kk * 68 + tx * 2];
                    b[1] = Bs[kk * 68 + tx * 2 + 1];
                    #pragma unroll
                    for (int i = 0; i < 4; i++) {
                        acc[i][0] += a[i] * b[0];
                        acc[i][1] += a[i] * b[1];
                    }
                }
                __syncthreads();
            }

            float bias0 = bout[fBase + tx * 2];
            float bias1 = bout[fBase + tx * 2 + 1];
            #pragma unroll
            for (int i = 0; i < 4; i++) {
                int b = ty * 4 + i;
                float2 ov;
                ov.x = acc[i][0] + bias0;
                ov.y = acc[i][1] + bias1;
                *(float2*)(out + ((size_t)b * SS + s) * FF + fBase + tx * 2) = ov;
            }
        }
        return;
    }

    // ---------------------- LSTM persist role ----------------------
    unsigned* hsu = (unsigned*)(sm + SM_HS);   // h tile, tf32 bits, pitch 516
    float* xg2 = sm + SM_XG;
    float* red = sm + SM_RED;                  // [b*16+j][20]: kw*4+g

    const int w = t >> 5, l = t & 31;
    const int kw = w >> 2, mw = w & 3;         // k-split, m-split
    const int gid = l >> 2, tig = l & 3;       // mma lane decode
    const int jgrp = blockIdx.x >> 2;
    const int bgrp = blockIdx.x & 3;
    const int jg0  = jgrp << 4;
    const int b0   = bgrp << 4;

    // Resident A fragments (W_hh rows, rna tf32)
    unsigned Af[16][4];
    {
        int m0 = (mw << 4) + gid;
        int m1 = m0 + 8;
        const float* r0 = Whh + (size_t)((m0 & 3) * HH + jg0 + (m0 >> 2)) * HH;
        const float* r1 = Whh + (size_t)((m1 & 3) * HH + jg0 + (m1 >> 2)) * HH;
        #pragma unroll
        for (int kt = 0; kt < 16; kt++) {
            int kc = (kw << 7) + (kt << 3) + tig;
            Af[kt][0] = f2tf32(__ldg(r0 + kc));
            Af[kt][1] = f2tf32(__ldg(r1 + kc));
            Af[kt][2] = f2tf32(__ldg(r0 + kc + 4));
            Af[kt][3] = f2tf32(__ldg(r1 + kc + 4));
        }
    }

    // Prefetch xg(0) and xg(1) (warps 0-7), separate commit groups
    if (t < 256) {
        int bi = t >> 4, cc = t & 15;
        int g = cc >> 2, j4 = cc & 3;
        {
            const float* src = g_xg + (size_t)(b0 + bi) * G4 + g * HH + jg0 + (j4 << 2);
            uint32_t d = (uint32_t)__cvta_generic_to_shared(
                &xg2[((g << 4) + bi) * 16 + (j4 << 2)]);
            CP16(d, src);
            asm volatile("cp.async.commit_group;");
        }
        {
            const float* src = g_xg + (size_t)(BB + b0 + bi) * G4 + g * HH + jg0 + (j4 << 2);
            uint32_t d = (uint32_t)__cvta_generic_to_shared(
                &xg2[1024 + ((g << 4) + bi) * 16 + (j4 << 2)]);
            CP16(d, src);
            asm volatile("cp.async.commit_group;");
        }
    }
    __syncthreads();

    float c = 0.f;

    for (int s = 0; s < SS; s++) {
        if (s > 0) {
            // h slice (tf32 bits straight from g_hist)
            {
                const float* hp = g_hist + ((size_t)(s - 1) << 15);
                #pragma unroll
                for (int it = 0; it < 4; it++) {
                    int idx = (it << 5) + l;
                    int r = idx >> 3, c8 = idx & 7;
                    int col = (kw << 7) + (mw << 5) + (c8 << 2);
                    uint32_t d = (uint32_t)__cvta_generic_to_shared(
                        &hsu[r * 516 + col]);
                    CP16(d, hp + ((size_t)(b0 + r) << 9) + col);
                }
                asm volatile("cp.async.commit_group;");
                asm volatile("cp.async.wait_group 0;");
                asm volatile("bar.sync %0, 128;" :: "r"(kw + 1));
            }

            // Prefetch xg(s+1) during compute (warps 0-7 only)
            if (t < 256 && s + 1 < SS) {
                int bi = t >> 4, cc = t & 15;
                int g = cc >> 2, j4 = cc & 3;
                const float* src = g_xg +
                    (size_t)((s + 1) * BB + b0 + bi) * G4 + g * HH + jg0 + (j4 << 2);
                uint32_t d = (uint32_t)__cvta_generic_to_shared(
                    &xg2[(((s + 1) & 1) << 10) + ((g << 4) + bi) * 16 + (j4 << 2)]);
                CP16(d, src);
                asm volatile("cp.async.commit_group;");
            }

            float C0[4] = {0.f, 0.f, 0.f, 0.f};
            float C1[4] = {0.f, 0.f, 0.f, 0.f};
            const unsigned* hb0 = hsu + gid * 516 + (kw << 7) + tig;
            const unsigned* hb1 = hsu + (gid + 8) * 516 + (kw << 7) + tig;
            #pragma unroll
            for (int kt = 0; kt < 16; kt++) {
                unsigned b0r = hb0[kt << 3];
                unsigned b1r = hb0[(kt << 3) + 4];
                MMA_TF32(C0, Af[kt], b0r, b1r);
                unsigned b2r = hb1[kt << 3];
                unsigned b3r = hb1[(kt << 3) + 4];
                MMA_TF32(C1, Af[kt], b2r, b3r);
            }

            // partials: red[(b*16+jl)*20 + kw*4+g]
            {
                const int jlA = (mw << 2) + (gid >> 2);
                const int gA  = gid & 3;
                const int bA  = tig << 1;
                const int cA  = (kw << 2) + gA;
                red[((bA)     * 16 + jlA)     * 20 + cA] = C0[0];
                red[((bA + 1) * 16 + jlA)     * 20 + cA] = C0[1];
                red[((bA)     * 16 + jlA + 2) * 20 + cA] = C0[2];
                red[((bA + 1) * 16 + jlA + 2) * 20 + cA] = C0[3];
                red[((bA + 8) * 16 + jlA)     * 20 + cA] = C1[0];
                red[((bA + 9) * 16 + jlA)     * 20 + cA] = C1[1];
                red[((bA + 8) * 16 + jlA + 2) * 20 + cA] = C1[2];
                red[((bA + 9) * 16 + jlA + 2) * 20 + cA] = C1[3];
            }
        } else {
            // xg(0) must be resident (xg(1) may still be in flight)
            if (t < 256) asm volatile("cp.async.wait_group 1;");
        }
        __syncthreads();   // red ready; hs reads complete

        if (t < 256) {
            // ---------------- owner phase (warps 0-7) ----------------
            const int jo = t & 15, bo = t >> 4;
            const float* xb = xg2 + ((s & 1) << 10);
            float a0 = xb[       (bo << 4) + jo];
            float a1 = xb[256 +  (bo << 4) + jo];
            float a2 = xb[512 +  (bo << 4) + jo];
            float a3 = xb[768 +  (bo << 4) + jo];
            if (s > 0) {
                const float4* rp = (const float4*)(red + t * 20);
                float4 q0 = rp[0], q1 = rp[1], q2 = rp[2], q3 = rp[3];
                a0 += q0.x + q1.x + q2.x + q3.x;
                a1 += q0.y + q1.y + q2.y + q3.y;
                a2 += q0.z + q1.z + q2.z + q3.z;
                a3 += q0.w + q1.w + q2.w + q3.w;
            }
            float ig = 1.f / (1.f + __expf(-a0));
            float fg = 1.f / (1.f + __expf(-a1));
            float gg = 2.f / (1.f + __expf(-2.f * a2)) - 1.f;
            float og = 1.f / (1.f + __expf(-a3));
            c = fg * c + ig * gg;
            float th = 2.f / (1.f + __expf(-2.f * c)) - 1.f;
            float h = og * th;
            // store tf32-rounded h (bits valid as mma operand AND as fp32)
            g_hist[((size_t)(s * BB + b0 + bo) << 9) + jg0 + jo] =
                __uint_as_float(f2tf32(h));

            asm volatile("bar.sync 9, 256;");
            if (t == 0)
                asm volatile("red.release.gpu.global.add.u32 [%0], %1;"
                             :: "l"(g_cnt + bgrp * SS + s), "r"(1u) : "memory");
        } else if (t == 256) {
            // overlapped producer poll (lane 0 of warp 8)
            const unsigned* ca = g_cnt + bgrp * SS + s;
            unsigned v;
            do {
                asm volatile("ld.acquire.gpu.global.u32 %0, [%1];"
                             : "=r"(v) : "l"(ca) : "memory");
            } while (v < NCTAG);
        }
        __syncthreads();   // owners released + producers verified -> next step
    }
}

extern "C" void kernel_launch(void* const* d_in, const int* in_sizes, int n_in,
                              void* d_out, int out_size)
{
    const float* inp  = (const float*)d_in[0];
    const float* Wih  = (const float*)d_in[1];
    const float* Whh  = (const float*)d_in[2];
    const float* bih  = (const float*)d_in[3];
    const float* bhh  = (const float*)d_in[4];
    const float* Wout = (const float*)d_in[5];
    const float* bout = (const float*)d_in[6];
    float* out = (float*)d_out;

    const int smem_bytes = SM_TOT * 4;    // 61,696 B
    const int xg_bytes   = XG_TOT * 4;    // 51,456 B
    cudaFuncSetAttribute(lstm_persist,
                         cudaFuncAttributeMaxDynamicSharedMemorySize, smem_bytes);
    cudaFuncSetAttribute(xg_tc,
                         cudaFuncAttributeMaxDynamicSharedMemorySize, xg_bytes);

    init_kernel<<<8, 256>>>();
    xg_tc<<<dim3(G4 / 64, 64), 256, xg_bytes>>>(inp, Wih, bih, bhh);
    lstm_persist<<<NCTA + NOUT, TPB, smem_bytes>>>(Whh, Wout, bout, out);
}